// round 17
// baseline (speedup 1.0000x reference)
#include <cuda_runtime.h>
#include <cuda_fp16.h>
#include <math.h>
#include <stdint.h>

// SwitchGate: logits = x @ W^T + b ; softmax ; top-2 mask ; masked/colsum*capacity
// N=262144, DIM=1024, E=64, TOP_K=2, capacity=N, EPS=1e-6
// Engine: fp16 2-term exact-x-split mma.sync ((x_h+x_m)*w_h; dropped x*w_m ~2.8e-4
// logit sigma), depth-2 cp.async stage pipeline, margin fixup (theta=10 sigma).
#define N_TOK 262144
#define DIMK  1024
#define NEXP  64
#define KCH   64
#define NCH   16
#define TM    128
#define THETA 3e-3f

// ---- device scratch (no allocation allowed) ----
__device__ float  g_denom[NEXP];
__device__ int    g_idx[N_TOK];
__device__ float2 g_val[N_TOK];
__device__ int    g_nflag;
__device__ int    g_flag[N_TOK];
// pre-swizzled fp16 W (single hi limb): [chunk][64 rows x 128B]
__device__ __align__(16) unsigned char g_wpre[NCH][NEXP * 128];
// K-major fp32 W transpose for the coalesced exact fixup: wT[k][e]
__device__ __align__(16) float g_wT[DIMK * NEXP];

__device__ __forceinline__ uint32_t smem_u32(const void* p) {
    uint32_t a;
    asm("{ .reg .u64 t; cvta.to.shared.u64 t, %1; cvt.u32.u64 %0, t; }" : "=r"(a) : "l"(p));
    return a;
}

#define LDSM4(r, a) \
    asm volatile("ldmatrix.sync.aligned.m8n8.x4.shared.b16 {%0,%1,%2,%3}, [%4];" \
        : "=r"((r)[0]), "=r"((r)[1]), "=r"((r)[2]), "=r"((r)[3]) : "r"(a))

#define MMA16816F16(cc, a, b0, b1) \
    asm volatile("mma.sync.aligned.m16n8k16.row.col.f32.f16.f16.f32 " \
        "{%0,%1,%2,%3}, {%4,%5,%6,%7}, {%8,%9}, {%0,%1,%2,%3};" \
        : "+f"((cc)[0]), "+f"((cc)[1]), "+f"((cc)[2]), "+f"((cc)[3]) \
        : "r"((a)[0]), "r"((a)[1]), "r"((a)[2]), "r"((a)[3]), "r"(b0), "r"(b1))

#define CP16(dst, src) \
    asm volatile("cp.async.cg.shared.global [%0], [%1], 16;" :: "r"(dst), "l"(src))
#define CP_COMMIT() asm volatile("cp.async.commit_group;" ::: "memory")
#define CP_WAIT(n)  asm volatile("cp.async.wait_group %0;" :: "n"(n) : "memory")

// fp16 split of W (pre-swizzled tiles) + fp32 K-major transpose + scratch zero.
__global__ void __launch_bounds__(256) prep_w_k(const float* __restrict__ W) {
    const int c = blockIdx.x;
    if (c == 0) {
        if (threadIdx.x < NEXP) g_denom[threadIdx.x] = 0.0f;
        if (threadIdx.x == 0)  g_nflag = 0;
    }
    for (int i = threadIdx.x; i < NEXP * KCH; i += 256) {
        const int e = i >> 6, kl = i & 63;
        const float v = W[(size_t)e * DIMK + c * KCH + kl];
        const unsigned byte = e * 128 + kl * 2;
        const unsigned sw = byte ^ ((byte >> 3) & 0x70);
        *(__half*)&g_wpre[c][sw] = __float2half_rn(v);
        g_wT[(size_t)(c * KCH + kl) * NEXP + e] = v;
    }
}

// dynamic smem (per CTA, 112KB):
//   XHI 0 (16K) | XMID 16K (16K) | WB0 32K (8K) | WB1 40K (8K)
//   STG0 48K (32K) | STG1 80K (32K)
#define XHI   0
#define XMID  16384
#define WB(s)  (32768 + (s) * 8192)
#define STG(s) (49152 + (s) * 32768)
#define SMEM_DYN 114688

// 128 threads, 4 warps; each warp computes m32 (rows 32*wid .. 32*wid+31).
// Sideband-only output (g_idx/g_val/g_denom/flags); rows built in scale_out_k.
__global__ void __launch_bounds__(128, 2) gate_main_k(
    const float* __restrict__ x,
    const float* __restrict__ b)
{
    extern __shared__ __align__(16) unsigned char smem[];
    const uint32_t sbase = smem_u32(smem);

    const int tid  = threadIdx.x;
    const int wid  = tid >> 5;
    const int lane = tid & 31;
    const int t0   = blockIdx.x * TM;
    const int m0   = wid * 32;           // warp's 32 token rows

    // A-frag lane addressing (m16k16, ldmatrix.x4): tile = lane>>3
    const int atile = lane >> 3;
    const int arow_b = m0 + (lane & 7) + ((atile & 1) << 3);  // + 16*mset
    const int ahalf  = atile >> 1;                 // 0/1 -> +16B (k8..15)
    const unsigned axor = (unsigned)(lane & 7) << 4;
    // B-frag lane addressing: jj offset = lane>>4, half = (lane>>3)&1
    const int bj_off = lane >> 4;
    const int bhalf  = (lane >> 3) & 1;
    const unsigned bxor = (unsigned)(lane & 7) << 4;

    // fill mapping: thread covers rows (tid>>4 + 8i), float4 col fkq
    const int frow0 = tid >> 4;   // 0..7
    const int fkq   = tid & 15;

    float cacc[2][8][4];
#pragma unroll
    for (int ms = 0; ms < 2; ms++)
#pragma unroll
        for (int j = 0; j < 8; j++)
#pragma unroll
            for (int i = 0; i < 4; i++) cacc[ms][j][i] = 0.0f;

    // ---- prologue: C0=[stage0+W0], C1=[stage1+W1] ----
#pragma unroll
    for (int cc = 0; cc < 2; cc++) {
#pragma unroll
        for (int i = 0; i < 16; i++) {
            const int row = frow0 + 8 * i;
            CP16(sbase + STG(cc) + row * 256 + fkq * 16,
                 x + (size_t)(t0 + row) * DIMK + cc * KCH + fkq * 4);
        }
#pragma unroll
        for (int i = 0; i < 4; i++) {
            const int off = tid + 128 * i;          // 0..511 int4
            CP16(sbase + WB(cc) + off * 16,
                 (const unsigned char*)g_wpre[cc] + off * 16);
        }
        CP_COMMIT();
    }

    for (int c = 0; c < NCH; ++c) {
        const int ssel = c & 1;
        __syncthreads();   // MMA(c-1) fully done (tiles + WB reuse safe)
        // ---- issue W(c+1) -> WB((c+1)&1): last read by MMA(c-1), done ----
        if (c >= 1 && c + 1 < NCH) {
#pragma unroll
            for (int i = 0; i < 4; i++) {
                const int off = tid + 128 * i;
                CP16(sbase + WB(ssel ^ 1) + off * 16,
                     (const unsigned char*)g_wpre[c + 1] + off * 16);
            }
            CP_COMMIT();
        }
        // ensure stage(c)+W(c) landed; newer groups stay in flight
        if (c == 0)            CP_WAIT(1);
        else if (c == NCH - 1) CP_WAIT(0);
        else                   CP_WAIT(2);

        // ---- convert stage fp32 -> fp16 hi/mid tiles (swizzled STS) ----
#pragma unroll
        for (int i = 0; i < 16; i++) {
            const int row = frow0 + 8 * i;
            const float4 v = *(const float4*)(smem + STG(ssel) + row * 256 + fkq * 16);
            const __half2 h01 = __floats2half2_rn(v.x, v.y);
            const __half2 h23 = __floats2half2_rn(v.z, v.w);
            const float r0 = v.x - __low2float(h01);
            const float r1 = v.y - __high2float(h01);
            const float r2 = v.z - __low2float(h23);
            const float r3 = v.w - __high2float(h23);
            const __half2 m01 = __floats2half2_rn(r0, r1);
            const __half2 m23 = __floats2half2_rn(r2, r3);
            const unsigned byte = row * 128 + fkq * 8;
            const unsigned sw = byte ^ ((byte >> 3) & 0x70);
            *(uint2*)(smem + XHI + sw) =
                make_uint2(*(const unsigned*)&h01, *(const unsigned*)&h23);
            *(uint2*)(smem + XMID + sw) =
                make_uint2(*(const unsigned*)&m01, *(const unsigned*)&m23);
        }
        // ---- issue stage(c+2) -> STG(ssel): per-thread slots just consumed ----
        if (c + 2 < NCH) {
            const int nxt = (c + 2) * KCH;
#pragma unroll
            for (int i = 0; i < 16; i++) {
                const int row = frow0 + 8 * i;
                CP16(sbase + STG(ssel) + row * 256 + fkq * 16,
                     x + (size_t)(t0 + row) * DIMK + nxt + fkq * 4);
            }
            CP_COMMIT();
        }
        __syncthreads();   // X tiles + WB(c) visible block-wide

        // ---- MMA: 4 ks x (4 B-LDSM + 2x(2 A-LDSM + 16 HMMA)) ----
        const uint32_t wb = sbase + WB(ssel);
#pragma unroll
        for (int ks = 0; ks < 4; ks++) {
            uint32_t bh[16];
#pragma unroll
            for (int jj = 0; jj < 4; jj++) {
                const unsigned brow = (unsigned)((2 * jj + bj_off) * 8 + (lane & 7));
                const unsigned bb = (brow * 128 + ks * 32 + bhalf * 16) ^ bxor;
                LDSM4(&bh[4 * jj], wb + bb);
            }
#pragma unroll
            for (int ms = 0; ms < 2; ms++) {
                uint32_t ah[4], am[4];
                const unsigned ab =
                    (unsigned)((arow_b + 16 * ms) * 128 + ks * 32 + ahalf * 16) ^ axor;
                LDSM4(ah, sbase + XHI + ab);
                LDSM4(am, sbase + XMID + ab);
#pragma unroll
                for (int j = 0; j < 8; j++) {
                    const int p = (j >> 1) * 4 + (j & 1) * 2;
                    MMA16816F16(cacc[ms][j], ah, bh[p], bh[p + 1]);  // x_h * w_h
                    MMA16816F16(cacc[ms][j], am, bh[p], bh[p + 1]);  // x_m * w_h
                }
            }
        }
    }

    // ---- epilogue: quad lanes hold rows m0+16*ms+8*rr+(lane>>2) ----
    const int q = lane & 3;
    const unsigned fullm = 0xffffffffu;
    float bq[16];
#pragma unroll
    for (int j = 0; j < 8; j++) {
        bq[2 * j]     = __ldg(b + 8 * j + 2 * q);
        bq[2 * j + 1] = __ldg(b + 8 * j + 2 * q + 1);
    }

#pragma unroll
    for (int ms = 0; ms < 2; ms++)
#pragma unroll
    for (int rr = 0; rr < 2; rr++) {
        const int row = m0 + 16 * ms + (lane >> 2) + rr * 8;
        float lv[16];
#pragma unroll
        for (int j = 0; j < 8; j++) {
            lv[2 * j]     = cacc[ms][j][2 * rr]     + bq[2 * j];
            lv[2 * j + 1] = cacc[ms][j][2 * rr + 1] + bq[2 * j + 1];
        }
        // local top2 (expert ids ascend with index -> strict > keeps lowest id)
        float v1 = lv[0]; int i1 = 2 * q;
        float v2 = -3.4e38f; int i2 = 127;
#pragma unroll
        for (int tq = 1; tq < 16; tq++) {
            const int e = 8 * (tq >> 1) + 2 * q + (tq & 1);
            const float v = lv[tq];
            if (v > v1)      { v2 = v1; i2 = i1; v1 = v; i1 = e; }
            else if (v > v2) { v2 = v;  i2 = e; }
        }
        // quad merge (ties -> lowest index)
#pragma unroll
        for (int d = 1; d < 4; d <<= 1) {
            const float ov1 = __shfl_xor_sync(fullm, v1, d);
            const int   oi1 = __shfl_xor_sync(fullm, i1, d);
            const float ov2 = __shfl_xor_sync(fullm, v2, d);
            const int   oi2 = __shfl_xor_sync(fullm, i2, d);
            const bool of = (ov1 > v1) || (ov1 == v1 && oi1 < i1);
            const float n1v = of ? ov1 : v1;  const int n1i = of ? oi1 : i1;
            const float c1v = of ? v1  : ov1; const int c1i = of ? i1  : oi1;
            const float c2v = of ? ov2 : v2;  const int c2i = of ? oi2 : i2;
            const bool sec = (c1v > c2v) || (c1v == c2v && c1i < c2i);
            v1 = n1v; i1 = n1i;
            v2 = sec ? c1v : c2v; i2 = sec ? c1i : c2i;
        }
        // sum of exp (v1 is the global max)
        float s = 0.0f;
#pragma unroll
        for (int tq = 0; tq < 16; tq++) s += __expf(lv[tq] - v1);
#pragma unroll
        for (int d = 1; d < 4; d <<= 1) s += __shfl_xor_sync(fullm, s, d);
        // third-best (margin)
        float v3 = -3.4e38f;
#pragma unroll
        for (int tq = 0; tq < 16; tq++) {
            const int e = 8 * (tq >> 1) + 2 * q + (tq & 1);
            if (e != i1 && e != i2) v3 = fmaxf(v3, lv[tq]);
        }
#pragma unroll
        for (int d = 1; d < 4; d <<= 1) v3 = fmaxf(v3, __shfl_xor_sync(fullm, v3, d));

        if (q == 0) {
            const float inv = 1.0f / s;
            const float gg1 = inv;                    // exp(v1-v1)=1
            const float gg2 = __expf(v2 - v1) * inv;
            const int t = t0 + row;
            atomicAdd(&g_denom[i1], gg1);
            atomicAdd(&g_denom[i2], gg2);
            g_idx[t] = i1 | (i2 << 8);
            g_val[t] = make_float2(gg1, gg2);
            if (v2 - v3 < THETA) {
                const int fi = atomicAdd(&g_nflag, 1);
                g_flag[fi] = t;
            }
        }
    }
}

// Exact fp32 recompute for margin-flagged tokens. The sequential-k fmaf order
// is load-bearing; 4-stage x 16-wide rotating register prefetch for MLP.
__global__ void __launch_bounds__(64) fixup_k(
    const float* __restrict__ x,
    const float* __restrict__ b)
{
    __shared__ __align__(16) float xs[DIMK];
    __shared__ float lg[NEXP];
    const int nf = g_nflag;
    const int e = threadIdx.x;
    for (int i = blockIdx.x; i < nf; i += gridDim.x) {
        const int t = g_flag[i];
        const float4* xsrc = (const float4*)(x + (size_t)t * DIMK);
#pragma unroll
        for (int p = 0; p < 4; p++)
            ((float4*)xs)[e + 64 * p] = xsrc[e + 64 * p];
        __syncthreads();
        const float* wp = g_wT + e;
        float acc = 0.f;
        float wbuf[64];
#pragma unroll
        for (int j = 0; j < 48; j++) wbuf[j] = wp[(size_t)j * NEXP];
#pragma unroll
        for (int g = 0; g < 64; g++) {
            const int sl = (g & 3) * 16;
            const int pf = ((g + 3) & 3) * 16;
            if (g < 61) {
#pragma unroll
                for (int j = 0; j < 16; j++)
                    wbuf[pf + j] = wp[(size_t)(g * 16 + 48 + j) * NEXP];
            }
#pragma unroll
            for (int j = 0; j < 16; j++)
                acc = fmaf(xs[g * 16 + j], wbuf[sl + j], acc);
        }
        lg[e] = acc + b[e];
        __syncthreads();
        if (e == 0) {
            float v1 = lg[0], v2 = -3.4e38f;
            int n1 = 0, n2 = -1;
            for (int j = 1; j < NEXP; j++) {
                const float v = lg[j];
                if (v > v1)      { v2 = v1; n2 = n1; v1 = v; n1 = j; }
                else if (v > v2) { v2 = v; n2 = j; }
            }
            const int old = g_idx[t];
            const int o1 = old & 255, o2 = old >> 8;
            const bool same = (o1 == n1 && o2 == n2) || (o1 == n2 && o2 == n1);
            if (!same) {
                float s = 0.f;
                for (int j = 0; j < NEXP; j++) s += expf(lg[j] - v1);
                const float ng1 = 1.0f / s;
                const float ng2 = expf(v2 - v1) / s;
                const float2 ov = g_val[t];
                atomicAdd(&g_denom[o1], -ov.x);
                atomicAdd(&g_denom[o2], -ov.y);
                atomicAdd(&g_denom[n1], ng1);
                atomicAdd(&g_denom[n2], ng2);
                g_idx[t] = n1 | (n2 << 8);
                g_val[t] = make_float2(ng1, ng2);
            }
        }
        __syncthreads();
    }
}

// Single coalesced output pass: build each full row from (idx, val) sideband
// with the capacity/denom scaling applied. 16 threads/token, float4 stores.
__global__ void __launch_bounds__(256) scale_out_k(float* __restrict__ out) {
    __shared__ float sc[NEXP];
    const int tid = threadIdx.x;
    if (tid < NEXP) sc[tid] = 262144.0f / (g_denom[tid] + 1e-6f);
    __syncthreads();
    const int t   = blockIdx.x * 16 + (tid >> 4);
    const int sub = tid & 15;
    const int packed = g_idx[t];
    const float2 g = g_val[t];
    const int i1 = packed & 255;
    const int i2 = packed >> 8;
    const float s1 = g.x * sc[i1];
    const float s2 = g.y * sc[i2];
    const int e0 = sub * 4;
    float4 w;
    w.x = (i1 == e0)     ? s1 : (i2 == e0)     ? s2 : 0.0f;
    w.y = (i1 == e0 + 1) ? s1 : (i2 == e0 + 1) ? s2 : 0.0f;
    w.z = (i1 == e0 + 2) ? s1 : (i2 == e0 + 2) ? s2 : 0.0f;
    w.w = (i1 == e0 + 3) ? s1 : (i2 == e0 + 3) ? s2 : 0.0f;
    *(float4*)(out + (size_t)t * NEXP + e0) = w;
}

extern "C" void kernel_launch(void* const* d_in, const int* in_sizes, int n_in,
                              void* d_out, int out_size) {
    const float* x = (const float*)d_in[0];
    const float* W = (const float*)d_in[1];
    const float* b = (const float*)d_in[2];
    float* out = (float*)d_out;

    cudaFuncSetAttribute(gate_main_k, cudaFuncAttributeMaxDynamicSharedMemorySize, SMEM_DYN);

    prep_w_k<<<NCH, 256>>>(W);
    gate_main_k<<<N_TOK / TM, 128, SMEM_DYN>>>(x, b);
    fixup_k<<<4096, 64>>>(x, b);
    scale_out_k<<<N_TOK / 16, 256>>>(out);
}